// round 3
// baseline (speedup 1.0000x reference)
#include <cuda_runtime.h>
#include <cstdint>

// Problem constants
static constexpr int B = 64;
static constexpr int T = 512;
static constexpr int D = 1024;
static constexpr int S = 1024;
static constexpr int U = 10;
static constexpr int NCH = 8;            // T-chunks per batch
static constexpr int TCH = T / NCH;      // 64 t per block
static constexpr int NBLK = B * NCH;     // 512 main blocks

// Scratch (device globals: no allocation allowed)
__device__ float g_u2[B * U];            // s_prev @ W1[D:] + b1, per batch
__device__ float g_cpart[NBLK * D];      // partial contexts (2 MB)
__device__ float g_e[B * T];             // exp(e) values

// ---------- packed f32x2 helpers (sm_103a) ----------
static __device__ __forceinline__ unsigned long long pack2(float x, float y) {
    unsigned long long r;
    asm("mov.b64 %0, {%1, %2};" : "=l"(r) : "f"(x), "f"(y));
    return r;
}
static __device__ __forceinline__ float2 unpack2(unsigned long long v) {
    float2 r;
    asm("mov.b64 {%0, %1}, %2;" : "=f"(r.x), "=f"(r.y) : "l"(v));
    return r;
}
static __device__ __forceinline__ unsigned long long fma2(
    unsigned long long a, unsigned long long b, unsigned long long c) {
    unsigned long long d;
    asm("fma.rn.f32x2 %0, %1, %2, %3;" : "=l"(d) : "l"(a), "l"(b), "l"(c));
    return d;
}

// accurate-enough tanh via exp identity (~1e-6 rel; tanh.approx risks 1e-3 gate)
static __device__ __forceinline__ float fast_tanh(float x) {
    float ex = __expf(2.0f * x);            // x<<0 -> 0 ; x>>0 -> inf : both limits OK
    return 1.0f - __fdividef(2.0f, ex + 1.0f);
}

// ---------- K0: u2[b][u] = s_prev[b] @ W1[D:, u] + b1[u] ----------
__global__ void k0_u2(const float* __restrict__ sp, const float* __restrict__ W1,
                      const float* __restrict__ b1) {
    int b = blockIdx.x;
    int tid = threadIdx.x;
    __shared__ float red[U][256];

    float4 s4 = *reinterpret_cast<const float4*>(sp + b * S + 4 * tid);
    const float* wb = W1 + (size_t)(D + 4 * tid) * U;

    float p[U];
#pragma unroll
    for (int u = 0; u < U; u++) {
        p[u] = s4.x * wb[u] + s4.y * wb[U + u] + s4.z * wb[2 * U + u] + s4.w * wb[3 * U + u];
    }
#pragma unroll
    for (int u = 0; u < U; u++) red[u][tid] = p[u];
    __syncthreads();

    int w = tid >> 5, j = tid & 31;
    for (int u = w; u < U; u += 8) {
        float s = 0.0f;
#pragma unroll
        for (int k = 0; k < 8; k++) s += red[u][j + 32 * k];
#pragma unroll
        for (int off = 16; off > 0; off >>= 1) s += __shfl_xor_sync(0xffffffffu, s, off);
        if (j == 0) g_u2[b * U + u] = s + b1[u];
    }
}

// ---------- K1: fused e + online (max-free) softmax-numerator + context partials ----------
// grid (NCH, B), 256 threads. Thread owns d = [4*tid, 4*tid+4). a read once from DRAM.
__global__ void __launch_bounds__(256, 2)
k1_main(const float* __restrict__ a, const float* __restrict__ W1,
        const float* __restrict__ W2, const float* __restrict__ b2) {
    int ch = blockIdx.x, b = blockIdx.y;
    int tid = threadIdx.x;

    __shared__ float part[2][U][256];
    __shared__ float hv[2][U];
    __shared__ float expv[2];
    __shared__ float cu2[U], cW2[U];
    __shared__ float cb2;

    if (tid < U) { cu2[tid] = g_u2[b * U + tid]; cW2[tid] = W2[tid]; }
    if (tid == 0) cb2 = b2[0];

    // register-resident packed weights for this thread's 4 d's
    unsigned long long w01[U], w23[U];
    {
        const float* wb = W1 + (size_t)(4 * tid) * U;
#pragma unroll
        for (int u = 0; u < U; u++) {
            w01[u] = pack2(wb[u], wb[U + u]);
            w23[u] = pack2(wb[2 * U + u], wb[3 * U + u]);
        }
    }
    unsigned long long c01 = 0ull, c23 = 0ull;   // context accumulator (bits 0 == {0.f,0.f})

    const float* abase = a + ((size_t)b * T + (size_t)ch * TCH) * D + 4 * tid;
    __syncthreads();   // consts visible

    // prefetch iteration 0 (two t's)
    float4 a0 = *reinterpret_cast<const float4*>(abase);
    float4 a1 = *reinterpret_cast<const float4*>(abase + D);

    const int w = tid >> 5, j = tid & 31;

    for (int it = 0; it < TCH / 2; it++) {
        unsigned long long A001 = pack2(a0.x, a0.y), A023 = pack2(a0.z, a0.w);
        unsigned long long A101 = pack2(a1.x, a1.y), A123 = pack2(a1.z, a1.w);

        // prefetch next pair (hide DRAM latency behind reduce phases)
        float4 n0 = a0, n1 = a1;
        if (it < TCH / 2 - 1) {
            n0 = *reinterpret_cast<const float4*>(abase + (size_t)(2 * it + 2) * D);
            n1 = *reinterpret_cast<const float4*>(abase + (size_t)(2 * it + 3) * D);
        }

        // per-thread partial dots: 2 t's x 10 u, packed f32x2
#pragma unroll
        for (int u = 0; u < U; u++) {
            unsigned long long q0 = fma2(A001, w01[u], 0ull);
            q0 = fma2(A023, w23[u], q0);
            float2 f0 = unpack2(q0);
            part[0][u][tid] = f0.x + f0.y;

            unsigned long long q1 = fma2(A101, w01[u], 0ull);
            q1 = fma2(A123, w23[u], q1);
            float2 f1 = unpack2(q1);
            part[1][u][tid] = f1.x + f1.y;
        }
        __syncthreads();

        // block reduce: warp w handles u = w (warps 0,1 also u = 8,9)
        for (int u = w; u < U; u += 8) {
#pragma unroll
            for (int tp = 0; tp < 2; tp++) {
                float s = 0.0f;
#pragma unroll
                for (int k = 0; k < 8; k++) s += part[tp][u][j + 32 * k];
#pragma unroll
                for (int off = 16; off > 0; off >>= 1) s += __shfl_xor_sync(0xffffffffu, s, off);
                if (j == 0) {
                    float hh = fast_tanh(s + cu2[u]);
                    hv[tp][u] = hh * cW2[u];
                }
            }
        }
        __syncthreads();

        // finalize e, exp(e) (max-free: e in [0, ~3] since |tanh|<=1)
        if (tid < 2) {
            float e = cb2;
#pragma unroll
            for (int u = 0; u < U; u++) e += hv[tid][u];
            e = fmaxf(e, 0.0f);
            float ex = __expf(e);
            expv[tid] = ex;
            g_e[b * T + ch * TCH + 2 * it + tid] = ex;
        }
        __syncthreads();

        // online numerator accumulation, reusing a registers
        float ex0 = expv[0], ex1 = expv[1];
        unsigned long long E0 = pack2(ex0, ex0), E1 = pack2(ex1, ex1);
        c01 = fma2(E0, A001, c01);
        c23 = fma2(E0, A023, c23);
        c01 = fma2(E1, A101, c01);
        c23 = fma2(E1, A123, c23);

        a0 = n0; a1 = n1;
    }

    // store partial context
    float2 lo = unpack2(c01), hi = unpack2(c23);
    float4 cv = make_float4(lo.x, lo.y, hi.x, hi.y);
    *reinterpret_cast<float4*>(g_cpart + ((size_t)(b * NCH + ch)) * D + 4 * tid) = cv;
}

// ---------- K2: combine chunk partials, normalize, write outputs ----------
__global__ void k2_combine(float* __restrict__ out, int scoreOff, int doScores) {
    int b = blockIdx.x;
    int tid = threadIdx.x;
    __shared__ float red[8];
    __shared__ float zinv;

    float e0 = g_e[b * T + tid];
    float e1 = g_e[b * T + 256 + tid];
    float s = e0 + e1;
#pragma unroll
    for (int off = 16; off > 0; off >>= 1) s += __shfl_xor_sync(0xffffffffu, s, off);
    if ((tid & 31) == 0) red[tid >> 5] = s;
    __syncthreads();
    if (tid == 0) {
        float z = 0.0f;
#pragma unroll
        for (int k = 0; k < 8; k++) z += red[k];
        zinv = 1.0f / z;     // z >= 512 (e >= 0 -> exp >= 1), no div-by-0
    }
    __syncthreads();
    float invZ = zinv;

    if (doScores) {
        out[scoreOff + b * T + tid] = e0 * invZ;
        out[scoreOff + b * T + 256 + tid] = e1 * invZ;
    }

    // context: sum 8 chunk partials for this thread's 4 d's
    float4 c = make_float4(0.f, 0.f, 0.f, 0.f);
#pragma unroll
    for (int ch = 0; ch < NCH; ch++) {
        float4 v = *reinterpret_cast<const float4*>(
            g_cpart + ((size_t)(b * NCH + ch)) * D + 4 * tid);
        c.x += v.x; c.y += v.y; c.z += v.z; c.w += v.w;
    }
    c.x *= invZ; c.y *= invZ; c.z *= invZ; c.w *= invZ;
    *reinterpret_cast<float4*>(out + (size_t)b * D + 4 * tid) = c;
}

extern "C" void kernel_launch(void* const* d_in, const int* in_sizes, int n_in,
                              void* d_out, int out_size) {
    const float* a   = (const float*)d_in[0];   // [B,T,D]
    const float* sp  = (const float*)d_in[1];   // [B,S]
    const float* W1  = (const float*)d_in[2];   // [D+S, 10]
    const float* b1  = (const float*)d_in[3];   // [10]
    const float* W2  = (const float*)d_in[4];   // [10, 1]
    const float* b2  = (const float*)d_in[5];   // [1]
    float* out = (float*)d_out;

    int scoreOff = B * D;
    int doScores = (out_size >= B * D + B * T) ? 1 : 0;

    k0_u2<<<B, 256>>>(sp, W1, b1);
    k1_main<<<dim3(NCH, B), 256>>>(a, W1, W2, b2);
    k2_combine<<<B, 256>>>(out, scoreOff, doScores);
}